// round 14
// baseline (speedup 1.0000x reference)
#include <cuda_runtime.h>
#include <cstdint>

#define NN 100000
#define NE 1000000
#define NB 500000
#define H  16
#define RND 5

#define SQ 258   // float4 pitch (258 % 8 == 2 -> conflict-free)

typedef unsigned long long ull;

// ---------------- scratch ---------------------------------------------------
__device__ __align__(16) float g_nf[NN * H];
__device__ __align__(16) float g_ef[NE * H];
__device__ __align__(16) float g_pre_s[NN * H];   // W1[:,0:16]  @ nf
__device__ __align__(16) float g_pre_r[NN * H];   // W1[:,16:32] @ nf + b1
__device__ __align__(16) float g_agg[NN * H];
__device__ float g_deg[NN];
__device__ int   g_win[NE];

// ---------------- helpers ---------------------------------------------------
__device__ __forceinline__ ull pk(float a, float b) {
    ull r; asm("mov.b64 %0,{%1,%2};" : "=l"(r) : "f"(a), "f"(b)); return r;
}
__device__ __forceinline__ float2 upk(ull a) {
    float2 f; asm("mov.b64 {%0,%1},%2;" : "=f"(f.x), "=f"(f.y) : "l"(a)); return f;
}
__device__ __forceinline__ ull fma2(ull a, ull b, ull c) {
    ull d; asm("fma.rn.f32x2 %0,%1,%2,%3;" : "=l"(d) : "l"(a), "l"(b), "l"(c)); return d;
}

__device__ __forceinline__ float4 ldg_cs4(const float4* p) {
    float4 v;
    asm volatile("ld.global.cs.v4.f32 {%0,%1,%2,%3}, [%4];"
                 : "=f"(v.x), "=f"(v.y), "=f"(v.z), "=f"(v.w) : "l"(p));
    return v;
}
__device__ __forceinline__ void stg_cs4(float4* p, float4 v) {
    asm volatile("st.global.cs.v4.f32 [%0], {%1,%2,%3,%4};"
                 :: "l"(p), "f"(v.x), "f"(v.y), "f"(v.z), "f"(v.w) : "memory");
}

__device__ __forceinline__ void ld16(const float* __restrict__ p, float* f) {
    const float4* q = (const float4*)p;
    float4 a = q[0], b = q[1], c = q[2], d = q[3];
    f[0]=a.x; f[1]=a.y; f[2]=a.z; f[3]=a.w;
    f[4]=b.x; f[5]=b.y; f[6]=b.z; f[7]=b.w;
    f[8]=c.x; f[9]=c.y; f[10]=c.z; f[11]=c.w;
    f[12]=d.x; f[13]=d.y; f[14]=d.z; f[15]=d.w;
}
__device__ __forceinline__ void st16(float* __restrict__ p, const float* f) {
    float4* q = (float4*)p;
    q[0] = make_float4(f[0], f[1], f[2], f[3]);
    q[1] = make_float4(f[4], f[5], f[6], f[7]);
    q[2] = make_float4(f[8], f[9], f[10], f[11]);
    q[3] = make_float4(f[12], f[13], f[14], f[15]);
}
__device__ __forceinline__ void red_add4(float* p, float4 v) {
    asm volatile("red.global.add.v4.f32 [%0], {%1,%2,%3,%4};"
                 :: "l"(p), "f"(v.x), "f"(v.y), "f"(v.z), "f"(v.w) : "memory");
}
__device__ __forceinline__ void red_deg(float* p) {
    asm volatile("red.global.add.f32 [%0], %1;" :: "l"(p), "f"(1.0f) : "memory");
}

__device__ __forceinline__ void pack8(const float* f, ull* xp) {
#pragma unroll
    for (int kk = 0; kk < 8; kk++) xp[kk] = pk(f[2*kk], f[2*kk+1]);
}

// single-vector 16-out GEMV, weights from smem as float4 (k-packed)
__device__ __forceinline__ void single16(const float4* __restrict__ w4, const ull* xp,
                                         const float* init, float* o, bool relu) {
#pragma unroll
    for (int oo = 0; oo < 16; oo++) {
        ull a = 0ULL;
#pragma unroll
        for (int q = 0; q < 4; q++) {
            float4 wv = w4[oo*4 + q];
            a = fma2(pk(wv.x, wv.y), xp[2*q],   a);
            a = fma2(pk(wv.z, wv.w), xp[2*q+1], a);
        }
        float2 f = upk(a);
        float v = init[oo] + f.x + f.y;
        o[oo] = relu ? fmaxf(v, 0.0f) : v;
    }
}

// ---------------- kernels ----------------------------------------------------
// node encoder: scalar->h->h, plus round-0 pre_s/pre_r, agg zeroing, deg zeroing
__global__ void k_encode_node(const float* __restrict__ x,
                              const float* __restrict__ W1, const float* __restrict__ b1,
                              const float* __restrict__ W2, const float* __restrict__ b2,
                              const float* __restrict__ mpW1, const float* __restrict__ mpB1) {
    __shared__ __align__(16) ull sW2p[128], sPSp[128], sPRp[128];
    __shared__ float sW1[16], sB1[16], sB2[16], sB1n[16], sZ[16];
    int tid = threadIdx.x;
    if (tid < 128) {
        int oo = tid >> 3, kk = tid & 7;
        sW2p[tid] = pk(W2[oo*16 + 2*kk],        W2[oo*16 + 2*kk + 1]);
        sPSp[tid] = pk(mpW1[oo*48 + 2*kk],      mpW1[oo*48 + 2*kk + 1]);
        sPRp[tid] = pk(mpW1[oo*48 + 16 + 2*kk], mpW1[oo*48 + 16 + 2*kk + 1]);
    }
    if (tid < 16) {
        sW1[tid] = W1[tid]; sB1[tid] = b1[tid]; sB2[tid] = b2[tid];
        sB1n[tid] = mpB1[tid]; sZ[tid] = 0.0f;
    }
    __syncthreads();
    int n = blockIdx.x * blockDim.x + tid;
    if (n >= NN) return;
    g_deg[n] = 0.0f;
    float xv = x[n];
    float h[16];
#pragma unroll
    for (int k = 0; k < 16; k++) h[k] = fmaxf(sW1[k] * xv + sB1[k], 0.0f);
    ull hp[8]; pack8(h, hp);
    float nf[16];
    single16((const float4*)sW2p, hp, sB2, nf, false);
    st16(&g_nf[(size_t)n * 16], nf);
    ull np[8]; pack8(nf, np);
    float ps[16], pr[16];
    single16((const float4*)sPSp, np, sZ,   ps, false);
    single16((const float4*)sPRp, np, sB1n, pr, false);
    st16(&g_pre_s[(size_t)n * 16], ps);
    st16(&g_pre_r[(size_t)n * 16], pr);
    float z[16];
#pragma unroll
    for (int k = 0; k < 16; k++) z[k] = 0.0f;
    st16(&g_agg[(size_t)n * 16], z);
}

// edge encoder: scalar->h->h, degree count, win init
__global__ void __launch_bounds__(256, 4)
k_encode_edge(const float* __restrict__ x,
              const float* __restrict__ W1, const float* __restrict__ b1,
              const float* __restrict__ W2, const float* __restrict__ b2,
              const int* __restrict__ recv) {
    __shared__ __align__(16) ull sW2p[128];
    __shared__ float sW1[16], sB1[16], sB2[16];
    int tid = threadIdx.x;
    if (tid < 128) {
        int oo = tid >> 3, kk = tid & 7;
        sW2p[tid] = pk(W2[oo*16 + 2*kk], W2[oo*16 + 2*kk + 1]);
    }
    if (tid < 16) { sW1[tid] = W1[tid]; sB1[tid] = b1[tid]; sB2[tid] = b2[tid]; }
    __syncthreads();
    int e = blockIdx.x * blockDim.x + tid;
    if (e >= NE) return;
    g_win[e] = -1;
    float xv = x[e];
    float h[16];
#pragma unroll
    for (int k = 0; k < 16; k++) h[k] = fmaxf(sW1[k] * xv + sB1[k], 0.0f);
    ull hp[8]; pack8(h, hp);
    float ef[16];
    single16((const float4*)sW2p, hp, sB2, ef, false);
    st16(&g_ef[(size_t)e * 16], ef);
    red_deg(&g_deg[recv[e]]);
}

// per-round edge update (R8 structure): 256-edge tile staged through smem,
// paired compute sharing weight LDS, .cs streaming hints on ef.
// Final round: no agg scatter (dead), and the bi-edge winner election rides
// in the tail instead (bi != nullptr), hiding k_bi's latency under compute.
__global__ void __launch_bounds__(256, 4)
k_edge(const int* __restrict__ snd, const int* __restrict__ rcv,
       const float* __restrict__ W1, const float* __restrict__ W2,
       const float* __restrict__ b2, int do_scatter, const int* __restrict__ bi) {
    __shared__ __align__(16) float4 sE[4 * SQ];
    __shared__ __align__(16) float4 sP[4 * SQ];
    __shared__ __align__(16) ull sW1t[128];   // [k][jpair]
    __shared__ __align__(16) ull sW2t[128];   // [g][k][j2]
    __shared__ __align__(16) ull sB2p[8];

    int tid = threadIdx.x;
    int base = blockIdx.x * 256;
    int nE = NE - base; if (nE > 256) nE = 256;

    if (tid < 128) {
        int k = tid >> 3, j = tid & 7;
        sW1t[k * 8 + j] = pk(W1[(2*j)*48 + 32 + k], W1[(2*j+1)*48 + 32 + k]);
        int g = tid >> 5, rem = tid & 31;
        int kk = rem >> 1, j2 = rem & 1;
        sW2t[tid] = pk(W2[(4*g + 2*j2)*16 + kk], W2[(4*g + 2*j2 + 1)*16 + kk]);
    }
    if (tid < 8) sB2p[tid] = pk(b2[2*tid], b2[2*tid+1]);

    const float4* gE = (const float4*)g_ef + (size_t)base * 4;
    const float4* gS = (const float4*)g_pre_s;
    const float4* gR = (const float4*)g_pre_r;
#pragma unroll
    for (int j = 0; j < 4; j++) {
        int g = j * 256 + tid;
        int e = g >> 2, seg = g & 3;
        if (e < nE) {
            sE[seg * SQ + e] = ldg_cs4(gE + g);
            int ns = snd[base + e];
            int nr = rcv[base + e];
            float4 a = gS[(size_t)ns * 4 + seg];
            float4 b = gR[(size_t)nr * 4 + seg];
            sP[seg * SQ + e] = make_float4(a.x + b.x, a.y + b.y, a.z + b.z, a.w + b.w);
        }
    }
    __syncthreads();

    if (tid < 128) {
        int eA = tid, eB = tid + 128;

        ull accA[8], accB[8];
#pragma unroll
        for (int j = 0; j < 8; j++) { accA[j] = 0ULL; accB[j] = 0ULL; }
#pragma unroll
        for (int c = 0; c < 4; c++) {
            float4 xvA = sE[c * SQ + eA];
            float4 xvB = sE[c * SQ + eB];
            const float* xa = (const float*)&xvA;
            const float* xb = (const float*)&xvB;
#pragma unroll
            for (int t = 0; t < 4; t++) {
                int k = 4*c + t;
                ull xxA = pk(xa[t], xa[t]);
                ull xxB = pk(xb[t], xb[t]);
                const ull* wr = &sW1t[k * 8];
#pragma unroll
                for (int j = 0; j < 8; j++) {
                    ull wv = wr[j];
                    accA[j] = fma2(wv, xxA, accA[j]);
                    accB[j] = fma2(wv, xxB, accB[j]);
                }
            }
        }
        float hA[16], hB[16];
#pragma unroll
        for (int c = 0; c < 4; c++) {
            float4 pA = sP[c * SQ + eA];
            float4 pB = sP[c * SQ + eB];
            float2 a0 = upk(accA[2*c]), a1 = upk(accA[2*c+1]);
            float2 b0 = upk(accB[2*c]), b1 = upk(accB[2*c+1]);
            hA[4*c+0] = fmaxf(a0.x + pA.x, 0.0f);
            hA[4*c+1] = fmaxf(a0.y + pA.y, 0.0f);
            hA[4*c+2] = fmaxf(a1.x + pA.z, 0.0f);
            hA[4*c+3] = fmaxf(a1.y + pA.w, 0.0f);
            hB[4*c+0] = fmaxf(b0.x + pB.x, 0.0f);
            hB[4*c+1] = fmaxf(b0.y + pB.y, 0.0f);
            hB[4*c+2] = fmaxf(b1.x + pB.z, 0.0f);
            hB[4*c+3] = fmaxf(b1.y + pB.w, 0.0f);
        }
#pragma unroll
        for (int g = 0; g < 4; g++) {
            ull aA0 = 0ULL, aA1 = 0ULL, aB0 = 0ULL, aB1 = 0ULL;
            const ull* w2 = &sW2t[g * 32];
#pragma unroll
            for (int k = 0; k < 16; k++) {
                ull w0 = w2[2*k], w1 = w2[2*k+1];
                ull xxA = pk(hA[k], hA[k]);
                ull xxB = pk(hB[k], hB[k]);
                aA0 = fma2(w0, xxA, aA0); aA1 = fma2(w1, xxA, aA1);
                aB0 = fma2(w0, xxB, aB0); aB1 = fma2(w1, xxB, aB1);
            }
            float2 f0 = upk(aA0), f1 = upk(aA1);
            float2 g0 = upk(aB0), g1 = upk(aB1);
            float2 c0 = upk(sB2p[2*g]), c1 = upk(sB2p[2*g+1]);
            sE[g * SQ + eA] = make_float4(f0.x + c0.x, f0.y + c0.y, f1.x + c1.x, f1.y + c1.y);
            sE[g * SQ + eB] = make_float4(g0.x + c0.x, g0.y + c0.y, g1.x + c1.x, g1.y + c1.y);
        }
    }
    __syncthreads();

    float4* gEo = (float4*)g_ef + (size_t)base * 4;
    if (do_scatter) {
#pragma unroll
        for (int j = 0; j < 4; j++) {
            int g = j * 256 + tid;
            int e = g >> 2, seg = g & 3;
            if (e < nE) {
                float4 v = sE[seg * SQ + e];
                stg_cs4(gEo + g, v);
                int nr = rcv[base + e];
                red_add4(&g_agg[(size_t)nr * 16 + seg * 4], v);
            }
        }
    } else {
#pragma unroll
        for (int j = 0; j < 4; j++) {
            int g = j * 256 + tid;
            int e = g >> 2;
            if (e < nE) stg_cs4(gEo + g, sE[(g & 3) * SQ + e]);
        }
        // bi-edge winner election folded into the final round's tail
        if (bi) {
            int p = base + tid;
            if (p < NB) {
                atomicMax(&g_win[bi[p]], p);
                atomicMax(&g_win[bi[NB + p]], (1 << 30) | p);
            }
        }
    }
}

// per-round node update: TWO threads per node (even/odd lanes of a warp),
// each computes 8 of 16 outputs per layer; half-exchanges via shfl.bfly.
__global__ void __launch_bounds__(256, 5)
k_node_upd(const float* __restrict__ W1, const float* __restrict__ b1,
           const float* __restrict__ W2, const float* __restrict__ b2,
           const float* __restrict__ nW1, const float* __restrict__ nB1) {
    __shared__ __align__(16) ull sW1t[256];   // [k 0..31][j 0..7]
    __shared__ __align__(16) ull sW2t[128];   // [k 0..15][j 0..7]
    __shared__ __align__(16) ull sPSt[128], sPRt[128];
    __shared__ __align__(16) ull sB1p[8], sB2p[8], sB1np[8];
    int tid = threadIdx.x;
    {
        int k = tid >> 3, j = tid & 7;   // k 0..31
        sW1t[tid] = pk(W1[(2*j)*32 + k], W1[(2*j+1)*32 + k]);
    }
    if (tid < 128) {
        int k = tid >> 3, j = tid & 7;   // k 0..15
        sW2t[tid] = pk(W2[(2*j)*16 + k], W2[(2*j+1)*16 + k]);
        sPSt[tid] = pk(nW1[(2*j)*48 + k],      nW1[(2*j+1)*48 + k]);
        sPRt[tid] = pk(nW1[(2*j)*48 + 16 + k], nW1[(2*j+1)*48 + 16 + k]);
    }
    if (tid < 8) {
        sB1p[tid]  = pk(b1[2*tid], b1[2*tid+1]);
        sB2p[tid]  = pk(b2[2*tid], b2[2*tid+1]);
        sB1np[tid] = pk(nB1[2*tid], nB1[2*tid+1]);
    }
    __syncthreads();

    int n = blockIdx.x * 128 + (tid >> 1);
    int half = tid & 1;
    if (n >= NN) return;
    int jb = half * 4;

    float inv = 1.0f / fmaxf(g_deg[n], 1.0f);
    const float4* gf = (const float4*)&g_nf[(size_t)n * 16];
    const float4* ga = (const float4*)&g_agg[(size_t)n * 16];

    ull acc[4];
#pragma unroll
    for (int j = 0; j < 4; j++) acc[j] = 0ULL;
#pragma unroll
    for (int c = 0; c < 4; c++) {
        float4 xv = gf[c];
        const float* xf = (const float*)&xv;
#pragma unroll
        for (int t = 0; t < 4; t++) {
            ull xx = pk(xf[t], xf[t]);
            const ull* wr = &sW1t[(4*c + t) * 8 + jb];
#pragma unroll
            for (int j = 0; j < 4; j++) acc[j] = fma2(wr[j], xx, acc[j]);
        }
    }
#pragma unroll
    for (int c = 0; c < 4; c++) {
        float4 av = ga[c];
        const float* af = (const float*)&av;
#pragma unroll
        for (int t = 0; t < 4; t++) {
            float a = af[t] * inv;
            ull xx = pk(a, a);
            const ull* wr = &sW1t[(16 + 4*c + t) * 8 + jb];
#pragma unroll
            for (int j = 0; j < 4; j++) acc[j] = fma2(wr[j], xx, acc[j]);
        }
    }
    float h_own[8];
#pragma unroll
    for (int j = 0; j < 4; j++) {
        float2 v = upk(acc[j]);
        float2 b = upk(sB1p[jb + j]);
        h_own[2*j]   = fmaxf(v.x + b.x, 0.0f);
        h_own[2*j+1] = fmaxf(v.y + b.y, 0.0f);
    }

    int kb_own = half * 8, kb_oth = (1 - half) * 8;
    ull acc2[4];
#pragma unroll
    for (int j = 0; j < 4; j++) acc2[j] = 0ULL;
#pragma unroll
    for (int i = 0; i < 8; i++) {
        ull xx = pk(h_own[i], h_own[i]);
        const ull* wr = &sW2t[(kb_own + i) * 8 + jb];
#pragma unroll
        for (int j = 0; j < 4; j++) acc2[j] = fma2(wr[j], xx, acc2[j]);
    }
#pragma unroll
    for (int i = 0; i < 8; i++) {
        float ho = __shfl_xor_sync(0xffffffffu, h_own[i], 1);
        ull xx = pk(ho, ho);
        const ull* wr = &sW2t[(kb_oth + i) * 8 + jb];
#pragma unroll
        for (int j = 0; j < 4; j++) acc2[j] = fma2(wr[j], xx, acc2[j]);
    }
    float o_own[8];
#pragma unroll
    for (int j = 0; j < 4; j++) {
        float2 v = upk(acc2[j]);
        float2 b = upk(sB2p[jb + j]);
        o_own[2*j]   = v.x + b.x;
        o_own[2*j+1] = v.y + b.y;
    }
    float4* dnf = (float4*)&g_nf[(size_t)n * 16 + half * 8];
    dnf[0] = make_float4(o_own[0], o_own[1], o_own[2], o_own[3]);
    dnf[1] = make_float4(o_own[4], o_own[5], o_own[6], o_own[7]);

    float o_oth[8];
#pragma unroll
    for (int i = 0; i < 8; i++) o_oth[i] = __shfl_xor_sync(0xffffffffu, o_own[i], 1);

    ull accS[4];
#pragma unroll
    for (int j = 0; j < 4; j++) accS[j] = 0ULL;
#pragma unroll
    for (int i = 0; i < 8; i++) {
        ull x0 = pk(o_own[i], o_own[i]);
        const ull* w0 = &sPSt[(kb_own + i) * 8 + jb];
        ull x1 = pk(o_oth[i], o_oth[i]);
        const ull* w1 = &sPSt[(kb_oth + i) * 8 + jb];
#pragma unroll
        for (int j = 0; j < 4; j++) {
            accS[j] = fma2(w0[j], x0, accS[j]);
            accS[j] = fma2(w1[j], x1, accS[j]);
        }
    }
    float4* dps = (float4*)&g_pre_s[(size_t)n * 16 + half * 8];
    {
        float2 v0 = upk(accS[0]), v1 = upk(accS[1]);
        float2 v2 = upk(accS[2]), v3 = upk(accS[3]);
        dps[0] = make_float4(v0.x, v0.y, v1.x, v1.y);
        dps[1] = make_float4(v2.x, v2.y, v3.x, v3.y);
    }

    ull accR[4];
#pragma unroll
    for (int j = 0; j < 4; j++) accR[j] = 0ULL;
#pragma unroll
    for (int i = 0; i < 8; i++) {
        ull x0 = pk(o_own[i], o_own[i]);
        const ull* w0 = &sPRt[(kb_own + i) * 8 + jb];
        ull x1 = pk(o_oth[i], o_oth[i]);
        const ull* w1 = &sPRt[(kb_oth + i) * 8 + jb];
#pragma unroll
        for (int j = 0; j < 4; j++) {
            accR[j] = fma2(w0[j], x0, accR[j]);
            accR[j] = fma2(w1[j], x1, accR[j]);
        }
    }
    float4* dpr = (float4*)&g_pre_r[(size_t)n * 16 + half * 8];
    {
        float2 v0 = upk(accR[0]), v1 = upk(accR[1]);
        float2 v2 = upk(accR[2]), v3 = upk(accR[3]);
        float2 b0 = upk(sB1np[jb]),     b1v = upk(sB1np[jb + 1]);
        float2 b2v = upk(sB1np[jb + 2]), b3 = upk(sB1np[jb + 3]);
        dpr[0] = make_float4(v0.x + b0.x, v0.y + b0.y, v1.x + b1v.x, v1.y + b1v.y);
        dpr[1] = make_float4(v2.x + b2v.x, v2.y + b2v.y, v3.x + b3.x, v3.y + b3.y);
    }

    float4* dag = (float4*)&g_agg[(size_t)n * 16 + half * 8];
    dag[0] = make_float4(0.f, 0.f, 0.f, 0.f);
    dag[1] = make_float4(0.f, 0.f, 0.f, 0.f);
}

// decode: staged bi-average gather (seg-grouped, 4 lanes per edge) into smem,
// then MLP h->h->1 + tril mask from smem.
__global__ void __launch_bounds__(256, 4)
k_dec(const int* __restrict__ snd, const int* __restrict__ rcv,
      const int* __restrict__ bi,
      const float* __restrict__ W1, const float* __restrict__ b1,
      const float* __restrict__ W2, const float* __restrict__ b2,
      float* __restrict__ out, int write_extra) {
    __shared__ __align__(16) float4 sF[4 * SQ];
    __shared__ __align__(16) ull sW1p[128];
    __shared__ float sB1[16], sW2[16], sB2;
    int tid = threadIdx.x;
    if (tid < 128) {
        int oo = tid >> 3, kk = tid & 7;
        sW1p[tid] = pk(W1[oo*16 + 2*kk], W1[oo*16 + 2*kk + 1]);
    }
    if (tid < 16) { sB1[tid] = b1[tid]; sW2[tid] = W2[tid]; }
    if (tid == 0) sB2 = b2[0];

    int base = blockIdx.x * 256;
    int nE = NE - base; if (nE > 256) nE = 256;
    const float4* gEf = (const float4*)g_ef;
#pragma unroll
    for (int j = 0; j < 4; j++) {
        int g = j * 256 + tid;
        int e = g >> 2, seg = g & 3;
        if (e < nE) {
            int w = g_win[base + e];
            float4 v;
            if (w >= 0) {
                int p = w & 0x3FFFFFFF;
                int i = bi[p], jn = bi[NB + p];
                float4 a = gEf[(size_t)i * 4 + seg];
                float4 b = gEf[(size_t)jn * 4 + seg];
                v = make_float4(0.5f*(a.x+b.x), 0.5f*(a.y+b.y),
                                0.5f*(a.z+b.z), 0.5f*(a.w+b.w));
            } else {
                v = gEf[(size_t)(base + e) * 4 + seg];
            }
            sF[seg * SQ + e] = v;
        }
    }
    __syncthreads();

    int e = base + tid;
    if (tid >= nE) return;
    float f[16];
#pragma unroll
    for (int seg = 0; seg < 4; seg++) {
        float4 v = sF[seg * SQ + tid];
        f[4*seg+0]=v.x; f[4*seg+1]=v.y; f[4*seg+2]=v.z; f[4*seg+3]=v.w;
    }
    ull fp[8]; pack8(f, fp);
    float h[16];
    single16((const float4*)sW1p, fp, sB1, h, true);
    float val = sB2;
#pragma unroll
    for (int o = 0; o < 16; o++) val += sW2[o] * h[o];
    int s = snd[e], r = rcv[e];
    out[e] = (r >= s) ? val : 0.0f;
    if (write_extra) {
        out[NE + e] = (float)r;
        out[2 * NE + e] = (float)s;
    }
}

// ---------------- launch -----------------------------------------------------
extern "C" void kernel_launch(void* const* d_in, const int* in_sizes, int n_in,
                              void* d_out, int out_size) {
    const float* nodes    = (const float*)d_in[0];
    const float* edges    = (const float*)d_in[1];
    const int*   receivers= (const int*)d_in[2];
    const int*   senders  = (const int*)d_in[3];
    const int*   bi       = (const int*)d_in[4];
    const float* neW1 = (const float*)d_in[5];
    const float* neB1 = (const float*)d_in[6];
    const float* neW2 = (const float*)d_in[7];
    const float* neB2 = (const float*)d_in[8];
    const float* eeW1 = (const float*)d_in[9];
    const float* eeB1 = (const float*)d_in[10];
    const float* eeW2 = (const float*)d_in[11];
    const float* eeB2 = (const float*)d_in[12];
    const float* meW1 = (const float*)d_in[13];  // [5][16][48]
    const float* meB1 = (const float*)d_in[14];
    const float* meW2 = (const float*)d_in[15];  // [5][16][16]
    const float* meB2 = (const float*)d_in[16];
    const float* mnW1 = (const float*)d_in[17];  // [5][16][32]
    const float* mnB1 = (const float*)d_in[18];
    const float* mnW2 = (const float*)d_in[19];
    const float* mnB2 = (const float*)d_in[20];
    const float* dW1  = (const float*)d_in[21];
    const float* dB1  = (const float*)d_in[22];
    const float* dW2  = (const float*)d_in[23];
    const float* dB2  = (const float*)d_in[24];

    const int TB = 256;
    const int gN  = (NN + TB - 1) / TB;
    const int gN2 = (NN + 127) / 128;      // 2 threads per node
    const int gE  = (NE + TB - 1) / TB;

    k_encode_node<<<gN, TB>>>(nodes, neW1, neB1, neW2, neB2, meW1, meB1);
    k_encode_edge<<<gE, TB>>>(edges, eeW1, eeB1, eeW2, eeB2, receivers);

    for (int r = 0; r < RND; r++) {
        int last = (r == RND - 1);
        k_edge<<<gE, TB>>>(senders, receivers,
                           meW1 + (size_t)r * 16 * 48,
                           meW2 + (size_t)r * 256,
                           meB2 + (size_t)r * 16,
                           last ? 0 : 1,
                           last ? bi : nullptr);
        if (!last) {
            k_node_upd<<<gN2, TB>>>(mnW1 + (size_t)r * 512, mnB1 + (size_t)r * 16,
                                    mnW2 + (size_t)r * 256, mnB2 + (size_t)r * 16,
                                    meW1 + (size_t)(r + 1) * 16 * 48,
                                    meB1 + (size_t)(r + 1) * 16);
        }
    }

    int write_extra = (out_size >= 3 * NE) ? 1 : 0;
    k_dec<<<gE, TB>>>(senders, receivers, bi, dW1, dB1, dW2, dB2,
                      (float*)d_out, write_extra);
}

// round 15
// speedup vs baseline: 1.0233x; 1.0233x over previous
#include <cuda_runtime.h>
#include <cstdint>

#define NN 100000
#define NE 1000000
#define NB 500000
#define H  16
#define RND 5

#define SQ 258   // float4 pitch (258 % 8 == 2 -> conflict-free)

typedef unsigned long long ull;

// ---------------- scratch ---------------------------------------------------
__device__ __align__(16) float g_nf[NN * H];
__device__ __align__(16) float g_ef[NE * H];
__device__ __align__(16) float g_pre_s[NN * H];   // W1[:,0:16]  @ nf
__device__ __align__(16) float g_pre_r[NN * H];   // W1[:,16:32] @ nf + b1
__device__ __align__(16) float g_agg[NN * H];
__device__ float g_deg[NN];
__device__ int   g_win[NE];

// ---------------- helpers ---------------------------------------------------
__device__ __forceinline__ ull pk(float a, float b) {
    ull r; asm("mov.b64 %0,{%1,%2};" : "=l"(r) : "f"(a), "f"(b)); return r;
}
__device__ __forceinline__ float2 upk(ull a) {
    float2 f; asm("mov.b64 {%0,%1},%2;" : "=f"(f.x), "=f"(f.y) : "l"(a)); return f;
}
__device__ __forceinline__ ull fma2(ull a, ull b, ull c) {
    ull d; asm("fma.rn.f32x2 %0,%1,%2,%3;" : "=l"(d) : "l"(a), "l"(b), "l"(c)); return d;
}

__device__ __forceinline__ float4 ldg_cs4(const float4* p) {
    float4 v;
    asm volatile("ld.global.cs.v4.f32 {%0,%1,%2,%3}, [%4];"
                 : "=f"(v.x), "=f"(v.y), "=f"(v.z), "=f"(v.w) : "l"(p));
    return v;
}
__device__ __forceinline__ void stg_cs4(float4* p, float4 v) {
    asm volatile("st.global.cs.v4.f32 [%0], {%1,%2,%3,%4};"
                 :: "l"(p), "f"(v.x), "f"(v.y), "f"(v.z), "f"(v.w) : "memory");
}

__device__ __forceinline__ void ld16(const float* __restrict__ p, float* f) {
    const float4* q = (const float4*)p;
    float4 a = q[0], b = q[1], c = q[2], d = q[3];
    f[0]=a.x; f[1]=a.y; f[2]=a.z; f[3]=a.w;
    f[4]=b.x; f[5]=b.y; f[6]=b.z; f[7]=b.w;
    f[8]=c.x; f[9]=c.y; f[10]=c.z; f[11]=c.w;
    f[12]=d.x; f[13]=d.y; f[14]=d.z; f[15]=d.w;
}
__device__ __forceinline__ void st16(float* __restrict__ p, const float* f) {
    float4* q = (float4*)p;
    q[0] = make_float4(f[0], f[1], f[2], f[3]);
    q[1] = make_float4(f[4], f[5], f[6], f[7]);
    q[2] = make_float4(f[8], f[9], f[10], f[11]);
    q[3] = make_float4(f[12], f[13], f[14], f[15]);
}
__device__ __forceinline__ void red_add4(float* p, float4 v) {
    asm volatile("red.global.add.v4.f32 [%0], {%1,%2,%3,%4};"
                 :: "l"(p), "f"(v.x), "f"(v.y), "f"(v.z), "f"(v.w) : "memory");
}
__device__ __forceinline__ void red_deg(float* p) {
    asm volatile("red.global.add.f32 [%0], %1;" :: "l"(p), "f"(1.0f) : "memory");
}

__device__ __forceinline__ void pack8(const float* f, ull* xp) {
#pragma unroll
    for (int kk = 0; kk < 8; kk++) xp[kk] = pk(f[2*kk], f[2*kk+1]);
}

// single-vector 16-out GEMV, weights from smem as float4 (k-packed)
__device__ __forceinline__ void single16(const float4* __restrict__ w4, const ull* xp,
                                         const float* init, float* o, bool relu) {
#pragma unroll
    for (int oo = 0; oo < 16; oo++) {
        ull a = 0ULL;
#pragma unroll
        for (int q = 0; q < 4; q++) {
            float4 wv = w4[oo*4 + q];
            a = fma2(pk(wv.x, wv.y), xp[2*q],   a);
            a = fma2(pk(wv.z, wv.w), xp[2*q+1], a);
        }
        float2 f = upk(a);
        float v = init[oo] + f.x + f.y;
        o[oo] = relu ? fmaxf(v, 0.0f) : v;
    }
}

// ---------------- kernels ----------------------------------------------------
// node encoder: scalar->h->h, plus round-0 pre_s/pre_r, agg zeroing, deg zeroing
__global__ void k_encode_node(const float* __restrict__ x,
                              const float* __restrict__ W1, const float* __restrict__ b1,
                              const float* __restrict__ W2, const float* __restrict__ b2,
                              const float* __restrict__ mpW1, const float* __restrict__ mpB1) {
    __shared__ __align__(16) ull sW2p[128], sPSp[128], sPRp[128];
    __shared__ float sW1[16], sB1[16], sB2[16], sB1n[16], sZ[16];
    int tid = threadIdx.x;
    if (tid < 128) {
        int oo = tid >> 3, kk = tid & 7;
        sW2p[tid] = pk(W2[oo*16 + 2*kk],        W2[oo*16 + 2*kk + 1]);
        sPSp[tid] = pk(mpW1[oo*48 + 2*kk],      mpW1[oo*48 + 2*kk + 1]);
        sPRp[tid] = pk(mpW1[oo*48 + 16 + 2*kk], mpW1[oo*48 + 16 + 2*kk + 1]);
    }
    if (tid < 16) {
        sW1[tid] = W1[tid]; sB1[tid] = b1[tid]; sB2[tid] = b2[tid];
        sB1n[tid] = mpB1[tid]; sZ[tid] = 0.0f;
    }
    __syncthreads();
    int n = blockIdx.x * blockDim.x + tid;
    if (n >= NN) return;
    g_deg[n] = 0.0f;
    float xv = x[n];
    float h[16];
#pragma unroll
    for (int k = 0; k < 16; k++) h[k] = fmaxf(sW1[k] * xv + sB1[k], 0.0f);
    ull hp[8]; pack8(h, hp);
    float nf[16];
    single16((const float4*)sW2p, hp, sB2, nf, false);
    st16(&g_nf[(size_t)n * 16], nf);
    ull np[8]; pack8(nf, np);
    float ps[16], pr[16];
    single16((const float4*)sPSp, np, sZ,   ps, false);
    single16((const float4*)sPRp, np, sB1n, pr, false);
    st16(&g_pre_s[(size_t)n * 16], ps);
    st16(&g_pre_r[(size_t)n * 16], pr);
    float z[16];
#pragma unroll
    for (int k = 0; k < 16; k++) z[k] = 0.0f;
    st16(&g_agg[(size_t)n * 16], z);
}

// edge encoder: scalar->h->h, degree count, win init
__global__ void __launch_bounds__(256, 4)
k_encode_edge(const float* __restrict__ x,
              const float* __restrict__ W1, const float* __restrict__ b1,
              const float* __restrict__ W2, const float* __restrict__ b2,
              const int* __restrict__ recv) {
    __shared__ __align__(16) ull sW2p[128];
    __shared__ float sW1[16], sB1[16], sB2[16];
    int tid = threadIdx.x;
    if (tid < 128) {
        int oo = tid >> 3, kk = tid & 7;
        sW2p[tid] = pk(W2[oo*16 + 2*kk], W2[oo*16 + 2*kk + 1]);
    }
    if (tid < 16) { sW1[tid] = W1[tid]; sB1[tid] = b1[tid]; sB2[tid] = b2[tid]; }
    __syncthreads();
    int e = blockIdx.x * blockDim.x + tid;
    if (e >= NE) return;
    g_win[e] = -1;
    float xv = x[e];
    float h[16];
#pragma unroll
    for (int k = 0; k < 16; k++) h[k] = fmaxf(sW1[k] * xv + sB1[k], 0.0f);
    ull hp[8]; pack8(h, hp);
    float ef[16];
    single16((const float4*)sW2p, hp, sB2, ef, false);
    st16(&g_ef[(size_t)e * 16], ef);
    red_deg(&g_deg[recv[e]]);
}

// per-round edge update (R8/R13 structure): 256-edge tile staged through smem,
// paired compute sharing weight LDS, .cs streaming hints on ef.
// do_scatter=0 for the FINAL round (agg never consumed afterwards).
// NEW: rcv cached in smem during staging -> scatter tail reads LDS instead of
// re-issuing 4 LDG.32 per edge on the binding L1 pipe.
__global__ void __launch_bounds__(256, 4)
k_edge(const int* __restrict__ snd, const int* __restrict__ rcv,
       const float* __restrict__ W1, const float* __restrict__ W2,
       const float* __restrict__ b2, int do_scatter) {
    __shared__ __align__(16) float4 sE[4 * SQ];
    __shared__ __align__(16) float4 sP[4 * SQ];
    __shared__ __align__(16) ull sW1t[128];   // [k][jpair]
    __shared__ __align__(16) ull sW2t[128];   // [g][k][j2]
    __shared__ __align__(16) ull sB2p[8];
    __shared__ int sRcv[256];

    int tid = threadIdx.x;
    int base = blockIdx.x * 256;
    int nE = NE - base; if (nE > 256) nE = 256;

    if (tid < 128) {
        int k = tid >> 3, j = tid & 7;
        sW1t[k * 8 + j] = pk(W1[(2*j)*48 + 32 + k], W1[(2*j+1)*48 + 33 + k - 1]);
        // note: identical to pk(W1[(2*j)*48+32+k], W1[(2*j+1)*48+32+k])
        sW1t[k * 8 + j] = pk(W1[(2*j)*48 + 32 + k], W1[(2*j+1)*48 + 32 + k]);
        int g = tid >> 5, rem = tid & 31;
        int kk = rem >> 1, j2 = rem & 1;
        sW2t[tid] = pk(W2[(4*g + 2*j2)*16 + kk], W2[(4*g + 2*j2 + 1)*16 + kk]);
    }
    if (tid < 8) sB2p[tid] = pk(b2[2*tid], b2[2*tid+1]);

    const float4* gE = (const float4*)g_ef + (size_t)base * 4;
    const float4* gS = (const float4*)g_pre_s;
    const float4* gR = (const float4*)g_pre_r;
#pragma unroll
    for (int j = 0; j < 4; j++) {
        int g = j * 256 + tid;
        int e = g >> 2, seg = g & 3;
        if (e < nE) {
            sE[seg * SQ + e] = ldg_cs4(gE + g);
            int ns = snd[base + e];
            int nr = rcv[base + e];
            if (seg == 0) sRcv[e] = nr;
            float4 a = gS[(size_t)ns * 4 + seg];
            float4 b = gR[(size_t)nr * 4 + seg];
            sP[seg * SQ + e] = make_float4(a.x + b.x, a.y + b.y, a.z + b.z, a.w + b.w);
        }
    }
    __syncthreads();

    if (tid < 128) {
        int eA = tid, eB = tid + 128;

        ull accA[8], accB[8];
#pragma unroll
        for (int j = 0; j < 8; j++) { accA[j] = 0ULL; accB[j] = 0ULL; }
#pragma unroll
        for (int c = 0; c < 4; c++) {
            float4 xvA = sE[c * SQ + eA];
            float4 xvB = sE[c * SQ + eB];
            const float* xa = (const float*)&xvA;
            const float* xb = (const float*)&xvB;
#pragma unroll
            for (int t = 0; t < 4; t++) {
                int k = 4*c + t;
                ull xxA = pk(xa[t], xa[t]);
                ull xxB = pk(xb[t], xb[t]);
                const ull* wr = &sW1t[k * 8];
#pragma unroll
                for (int j = 0; j < 8; j++) {
                    ull wv = wr[j];
                    accA[j] = fma2(wv, xxA, accA[j]);
                    accB[j] = fma2(wv, xxB, accB[j]);
                }
            }
        }
        float hA[16], hB[16];
#pragma unroll
        for (int c = 0; c < 4; c++) {
            float4 pA = sP[c * SQ + eA];
            float4 pB = sP[c * SQ + eB];
            float2 a0 = upk(accA[2*c]), a1 = upk(accA[2*c+1]);
            float2 b0 = upk(accB[2*c]), b1 = upk(accB[2*c+1]);
            hA[4*c+0] = fmaxf(a0.x + pA.x, 0.0f);
            hA[4*c+1] = fmaxf(a0.y + pA.y, 0.0f);
            hA[4*c+2] = fmaxf(a1.x + pA.z, 0.0f);
            hA[4*c+3] = fmaxf(a1.y + pA.w, 0.0f);
            hB[4*c+0] = fmaxf(b0.x + pB.x, 0.0f);
            hB[4*c+1] = fmaxf(b0.y + pB.y, 0.0f);
            hB[4*c+2] = fmaxf(b1.x + pB.z, 0.0f);
            hB[4*c+3] = fmaxf(b1.y + pB.w, 0.0f);
        }
#pragma unroll
        for (int g = 0; g < 4; g++) {
            ull aA0 = 0ULL, aA1 = 0ULL, aB0 = 0ULL, aB1 = 0ULL;
            const ull* w2 = &sW2t[g * 32];
#pragma unroll
            for (int k = 0; k < 16; k++) {
                ull w0 = w2[2*k], w1 = w2[2*k+1];
                ull xxA = pk(hA[k], hA[k]);
                ull xxB = pk(hB[k], hB[k]);
                aA0 = fma2(w0, xxA, aA0); aA1 = fma2(w1, xxA, aA1);
                aB0 = fma2(w0, xxB, aB0); aB1 = fma2(w1, xxB, aB1);
            }
            float2 f0 = upk(aA0), f1 = upk(aA1);
            float2 g0 = upk(aB0), g1 = upk(aB1);
            float2 c0 = upk(sB2p[2*g]), c1 = upk(sB2p[2*g+1]);
            sE[g * SQ + eA] = make_float4(f0.x + c0.x, f0.y + c0.y, f1.x + c1.x, f1.y + c1.y);
            sE[g * SQ + eB] = make_float4(g0.x + c0.x, g0.y + c0.y, g1.x + c1.x, g1.y + c1.y);
        }
    }
    __syncthreads();

    float4* gEo = (float4*)g_ef + (size_t)base * 4;
    if (do_scatter) {
#pragma unroll
        for (int j = 0; j < 4; j++) {
            int g = j * 256 + tid;
            int e = g >> 2, seg = g & 3;
            if (e < nE) {
                float4 v = sE[seg * SQ + e];
                stg_cs4(gEo + g, v);
                int nr = sRcv[e];
                red_add4(&g_agg[(size_t)nr * 16 + seg * 4], v);
            }
        }
    } else {
#pragma unroll
        for (int j = 0; j < 4; j++) {
            int g = j * 256 + tid;
            int e = g >> 2;
            if (e < nE) stg_cs4(gEo + g, sE[(g & 3) * SQ + e]);
        }
    }
}

// per-round node update: TWO threads per node (even/odd lanes of a warp),
// each computes 8 of 16 outputs per layer; half-exchanges via shfl.bfly.
__global__ void __launch_bounds__(256, 5)
k_node_upd(const float* __restrict__ W1, const float* __restrict__ b1,
           const float* __restrict__ W2, const float* __restrict__ b2,
           const float* __restrict__ nW1, const float* __restrict__ nB1) {
    __shared__ __align__(16) ull sW1t[256];   // [k 0..31][j 0..7]
    __shared__ __align__(16) ull sW2t[128];   // [k 0..15][j 0..7]
    __shared__ __align__(16) ull sPSt[128], sPRt[128];
    __shared__ __align__(16) ull sB1p[8], sB2p[8], sB1np[8];
    int tid = threadIdx.x;
    {
        int k = tid >> 3, j = tid & 7;   // k 0..31
        sW1t[tid] = pk(W1[(2*j)*32 + k], W1[(2*j+1)*32 + k]);
    }
    if (tid < 128) {
        int k = tid >> 3, j = tid & 7;   // k 0..15
        sW2t[tid] = pk(W2[(2*j)*16 + k], W2[(2*j+1)*16 + k]);
        sPSt[tid] = pk(nW1[(2*j)*48 + k],      nW1[(2*j+1)*48 + k]);
        sPRt[tid] = pk(nW1[(2*j)*48 + 16 + k], nW1[(2*j+1)*48 + 16 + k]);
    }
    if (tid < 8) {
        sB1p[tid]  = pk(b1[2*tid], b1[2*tid+1]);
        sB2p[tid]  = pk(b2[2*tid], b2[2*tid+1]);
        sB1np[tid] = pk(nB1[2*tid], nB1[2*tid+1]);
    }
    __syncthreads();

    int n = blockIdx.x * 128 + (tid >> 1);
    int half = tid & 1;
    if (n >= NN) return;
    int jb = half * 4;

    float inv = 1.0f / fmaxf(g_deg[n], 1.0f);
    const float4* gf = (const float4*)&g_nf[(size_t)n * 16];
    const float4* ga = (const float4*)&g_agg[(size_t)n * 16];

    ull acc[4];
#pragma unroll
    for (int j = 0; j < 4; j++) acc[j] = 0ULL;
#pragma unroll
    for (int c = 0; c < 4; c++) {
        float4 xv = gf[c];
        const float* xf = (const float*)&xv;
#pragma unroll
        for (int t = 0; t < 4; t++) {
            ull xx = pk(xf[t], xf[t]);
            const ull* wr = &sW1t[(4*c + t) * 8 + jb];
#pragma unroll
            for (int j = 0; j < 4; j++) acc[j] = fma2(wr[j], xx, acc[j]);
        }
    }
#pragma unroll
    for (int c = 0; c < 4; c++) {
        float4 av = ga[c];
        const float* af = (const float*)&av;
#pragma unroll
        for (int t = 0; t < 4; t++) {
            float a = af[t] * inv;
            ull xx = pk(a, a);
            const ull* wr = &sW1t[(16 + 4*c + t) * 8 + jb];
#pragma unroll
            for (int j = 0; j < 4; j++) acc[j] = fma2(wr[j], xx, acc[j]);
        }
    }
    float h_own[8];
#pragma unroll
    for (int j = 0; j < 4; j++) {
        float2 v = upk(acc[j]);
        float2 b = upk(sB1p[jb + j]);
        h_own[2*j]   = fmaxf(v.x + b.x, 0.0f);
        h_own[2*j+1] = fmaxf(v.y + b.y, 0.0f);
    }

    int kb_own = half * 8, kb_oth = (1 - half) * 8;
    ull acc2[4];
#pragma unroll
    for (int j = 0; j < 4; j++) acc2[j] = 0ULL;
#pragma unroll
    for (int i = 0; i < 8; i++) {
        ull xx = pk(h_own[i], h_own[i]);
        const ull* wr = &sW2t[(kb_own + i) * 8 + jb];
#pragma unroll
        for (int j = 0; j < 4; j++) acc2[j] = fma2(wr[j], xx, acc2[j]);
    }
#pragma unroll
    for (int i = 0; i < 8; i++) {
        float ho = __shfl_xor_sync(0xffffffffu, h_own[i], 1);
        ull xx = pk(ho, ho);
        const ull* wr = &sW2t[(kb_oth + i) * 8 + jb];
#pragma unroll
        for (int j = 0; j < 4; j++) acc2[j] = fma2(wr[j], xx, acc2[j]);
    }
    float o_own[8];
#pragma unroll
    for (int j = 0; j < 4; j++) {
        float2 v = upk(acc2[j]);
        float2 b = upk(sB2p[jb + j]);
        o_own[2*j]   = v.x + b.x;
        o_own[2*j+1] = v.y + b.y;
    }
    float4* dnf = (float4*)&g_nf[(size_t)n * 16 + half * 8];
    dnf[0] = make_float4(o_own[0], o_own[1], o_own[2], o_own[3]);
    dnf[1] = make_float4(o_own[4], o_own[5], o_own[6], o_own[7]);

    float o_oth[8];
#pragma unroll
    for (int i = 0; i < 8; i++) o_oth[i] = __shfl_xor_sync(0xffffffffu, o_own[i], 1);

    ull accS[4];
#pragma unroll
    for (int j = 0; j < 4; j++) accS[j] = 0ULL;
#pragma unroll
    for (int i = 0; i < 8; i++) {
        ull x0 = pk(o_own[i], o_own[i]);
        const ull* w0 = &sPSt[(kb_own + i) * 8 + jb];
        ull x1 = pk(o_oth[i], o_oth[i]);
        const ull* w1 = &sPSt[(kb_oth + i) * 8 + jb];
#pragma unroll
        for (int j = 0; j < 4; j++) {
            accS[j] = fma2(w0[j], x0, accS[j]);
            accS[j] = fma2(w1[j], x1, accS[j]);
        }
    }
    float4* dps = (float4*)&g_pre_s[(size_t)n * 16 + half * 8];
    {
        float2 v0 = upk(accS[0]), v1 = upk(accS[1]);
        float2 v2 = upk(accS[2]), v3 = upk(accS[3]);
        dps[0] = make_float4(v0.x, v0.y, v1.x, v1.y);
        dps[1] = make_float4(v2.x, v2.y, v3.x, v3.y);
    }

    ull accR[4];
#pragma unroll
    for (int j = 0; j < 4; j++) accR[j] = 0ULL;
#pragma unroll
    for (int i = 0; i < 8; i++) {
        ull x0 = pk(o_own[i], o_own[i]);
        const ull* w0 = &sPRt[(kb_own + i) * 8 + jb];
        ull x1 = pk(o_oth[i], o_oth[i]);
        const ull* w1 = &sPRt[(kb_oth + i) * 8 + jb];
#pragma unroll
        for (int j = 0; j < 4; j++) {
            accR[j] = fma2(w0[j], x0, accR[j]);
            accR[j] = fma2(w1[j], x1, accR[j]);
        }
    }
    float4* dpr = (float4*)&g_pre_r[(size_t)n * 16 + half * 8];
    {
        float2 v0 = upk(accR[0]), v1 = upk(accR[1]);
        float2 v2 = upk(accR[2]), v3 = upk(accR[3]);
        float2 b0 = upk(sB1np[jb]),     b1v = upk(sB1np[jb + 1]);
        float2 b2v = upk(sB1np[jb + 2]), b3 = upk(sB1np[jb + 3]);
        dpr[0] = make_float4(v0.x + b0.x, v0.y + b0.y, v1.x + b1v.x, v1.y + b1v.y);
        dpr[1] = make_float4(v2.x + b2v.x, v2.y + b2v.y, v3.x + b3.x, v3.y + b3.y);
    }

    float4* dag = (float4*)&g_agg[(size_t)n * 16 + half * 8];
    dag[0] = make_float4(0.f, 0.f, 0.f, 0.f);
    dag[1] = make_float4(0.f, 0.f, 0.f, 0.f);
}

// bi-edge averaging winner election (sequential last-write-wins semantics)
__global__ void k_bi(const int* __restrict__ bi) {
    int p = blockIdx.x * blockDim.x + threadIdx.x;
    if (p >= NB) return;
    atomicMax(&g_win[bi[p]], p);
    atomicMax(&g_win[bi[NB + p]], (1 << 30) | p);
}

// decode: bi-average from pre-decode ef, MLP h->h->1, tril mask
__global__ void __launch_bounds__(256, 4)
k_dec(const int* __restrict__ snd, const int* __restrict__ rcv,
      const int* __restrict__ bi,
      const float* __restrict__ W1, const float* __restrict__ b1,
      const float* __restrict__ W2, const float* __restrict__ b2,
      float* __restrict__ out, int write_extra) {
    __shared__ __align__(16) ull sW1p[128];
    __shared__ float sB1[16], sW2[16], sB2;
    int tid = threadIdx.x;
    if (tid < 128) {
        int oo = tid >> 3, kk = tid & 7;
        sW1p[tid] = pk(W1[oo*16 + 2*kk], W1[oo*16 + 2*kk + 1]);
    }
    if (tid < 16) { sB1[tid] = b1[tid]; sW2[tid] = W2[tid]; }
    if (tid == 0) sB2 = b2[0];
    __syncthreads();
    int e = blockIdx.x * blockDim.x + tid;
    if (e >= NE) return;
    float f[16];
    int w = g_win[e];
    if (w >= 0) {
        int p = w & 0x3FFFFFFF;
        int i = bi[p], j = bi[NB + p];
        float fi[16], fj[16];
        ld16(&g_ef[(size_t)i * 16], fi);
        ld16(&g_ef[(size_t)j * 16], fj);
#pragma unroll
        for (int k = 0; k < 16; k++) f[k] = 0.5f * (fi[k] + fj[k]);
    } else {
        ld16(&g_ef[(size_t)e * 16], f);
    }
    ull fp[8]; pack8(f, fp);
    float h[16];
    single16((const float4*)sW1p, fp, sB1, h, true);
    float val = sB2;
#pragma unroll
    for (int o = 0; o < 16; o++) val += sW2[o] * h[o];
    int s = snd[e], r = rcv[e];
    out[e] = (r >= s) ? val : 0.0f;
    if (write_extra) {
        out[NE + e] = (float)r;
        out[2 * NE + e] = (float)s;
    }
}

// ---------------- launch -----------------------------------------------------
extern "C" void kernel_launch(void* const* d_in, const int* in_sizes, int n_in,
                              void* d_out, int out_size) {
    const float* nodes    = (const float*)d_in[0];
    const float* edges    = (const float*)d_in[1];
    const int*   receivers= (const int*)d_in[2];
    const int*   senders  = (const int*)d_in[3];
    const int*   bi       = (const int*)d_in[4];
    const float* neW1 = (const float*)d_in[5];
    const float* neB1 = (const float*)d_in[6];
    const float* neW2 = (const float*)d_in[7];
    const float* neB2 = (const float*)d_in[8];
    const float* eeW1 = (const float*)d_in[9];
    const float* eeB1 = (const float*)d_in[10];
    const float* eeW2 = (const float*)d_in[11];
    const float* eeB2 = (const float*)d_in[12];
    const float* meW1 = (const float*)d_in[13];  // [5][16][48]
    const float* meB1 = (const float*)d_in[14];
    const float* meW2 = (const float*)d_in[15];  // [5][16][16]
    const float* meB2 = (const float*)d_in[16];
    const float* mnW1 = (const float*)d_in[17];  // [5][16][32]
    const float* mnB1 = (const float*)d_in[18];
    const float* mnW2 = (const float*)d_in[19];
    const float* mnB2 = (const float*)d_in[20];
    const float* dW1  = (const float*)d_in[21];
    const float* dB1  = (const float*)d_in[22];
    const float* dW2  = (const float*)d_in[23];
    const float* dB2  = (const float*)d_in[24];

    const int TB = 256;
    const int gN  = (NN + TB - 1) / TB;
    const int gN2 = (NN + 127) / 128;      // 2 threads per node
    const int gE  = (NE + TB - 1) / TB;
    const int gB  = (NB + TB - 1) / TB;

    k_encode_node<<<gN, TB>>>(nodes, neW1, neB1, neW2, neB2, meW1, meB1);
    k_encode_edge<<<gE, TB>>>(edges, eeW1, eeB1, eeW2, eeB2, receivers);
    k_bi<<<gB, TB>>>(bi);   // independent of rounds; off the critical tail

    for (int r = 0; r < RND; r++) {
        int last = (r == RND - 1);
        k_edge<<<gE, TB>>>(senders, receivers,
                           meW1 + (size_t)r * 16 * 48,
                           meW2 + (size_t)r * 256,
                           meB2 + (size_t)r * 16,
                           last ? 0 : 1);
        if (!last) {
            k_node_upd<<<gN2, TB>>>(mnW1 + (size_t)r * 512, mnB1 + (size_t)r * 16,
                                    mnW2 + (size_t)r * 256, mnB2 + (size_t)r * 16,
                                    meW1 + (size_t)(r + 1) * 16 * 48,
                                    meB1 + (size_t)(r + 1) * 16);
        }
    }

    int write_extra = (out_size >= 3 * NE) ? 1 : 0;
    k_dec<<<gE, TB>>>(senders, receivers, bi, dW1, dB1, dW2, dB2,
                      (float*)d_out, write_extra);
}